// round 8
// baseline (speedup 1.0000x reference)
#include <cuda_runtime.h>

#define THREADS 512
#define TB 32
#define MROWS 96
#define LDA 104
#define LDWT 104
#define DM 100
#define DIN 72
#define FFD 512
#define NLAYERS 8
#define NCLS 40

// smem float offsets
#define SX 0
#define SQ 9984
#define SK 19968
#define SV 29952
#define SWT 39936
#define SMEM_FLOATS 50784   // 203,136 bytes

typedef unsigned long long ull;

__device__ __forceinline__ void ffma2(ull& acc, ull a, ull b) {
  asm("fma.rn.f32x2 %0, %1, %2, %0;" : "+l"(acc) : "l"(a), "l"(b));
}
__device__ __forceinline__ ull pack2(float x, float y) {
  ull r; asm("mov.b64 %0, {%1, %2};" : "=l"(r) : "f"(x), "f"(y)); return r;
}
__device__ __forceinline__ void upk2(ull v, float& lo, float& hi) {
  asm("mov.b64 {%0, %1}, %2;" : "=f"(lo), "=f"(hi) : "l"(v));
}

__device__ __forceinline__ int kmid(int K) { return ((K >> 1) + 3) & ~3; }

// Stage W transposed: Wt[k][n] = (n < nvalid) ? src[n*sstride + k] : 0, k < K (mult of 4).
// Participating threads: local ids [0, stride) mapped from caller.
__device__ __forceinline__ void stage_wt(float* wt, const float* __restrict__ src,
                                         int sstride, int nvalid, int K,
                                         int ltid, int stride) {
  const int total = (K >> 2) * 104;
  for (int idx = ltid; idx < total; idx += stride) {
    int kc = idx / 104;
    int n = idx - kc * 104;
    float4 v = make_float4(0.f, 0.f, 0.f, 0.f);
    if (n < nvalid) v = *reinterpret_cast<const float4*>(src + n * sstride + 4 * kc);
    int kb = 4 * kc;
    wt[(kb + 0) * LDWT + n] = v.x;
    wt[(kb + 1) * LDWT + n] = v.y;
    wt[(kb + 2) * LDWT + n] = v.z;
    wt[(kb + 3) * LDWT + n] = v.w;
  }
}

// C[m][n] += sum_{k in [kb,ke)} A[m][k] * Wt[k][n]
// thread (tm,tn): rows {tm+16r}, cols {4tn..4tn+3} u {52+4tn..52+4tn+3}
__device__ __forceinline__ void gemm_cp(const float* __restrict__ A,
                                        const float* __restrict__ Wt,
                                        int kb, int ke, ull (&acc)[6][4], int tm, int tn) {
  const float* a0 = A + tm * LDA;
  const int c0 = 4 * tn, c1 = 52 + 4 * tn;
#pragma unroll 2
  for (int k = kb; k < ke; k += 4) {
    float4 a[6];
#pragma unroll
    for (int r = 0; r < 6; r++)
      a[r] = *reinterpret_cast<const float4*>(a0 + (16 * r) * LDA + k);
#pragma unroll
    for (int kk = 0; kk < 4; kk++) {
      const float* wrow = Wt + (k + kk) * LDWT;
      float4 w0 = *reinterpret_cast<const float4*>(wrow + c0);
      float4 w1 = *reinterpret_cast<const float4*>(wrow + c1);
      ull w00 = pack2(w0.x, w0.y), w01 = pack2(w0.z, w0.w);
      ull w10 = pack2(w1.x, w1.y), w11 = pack2(w1.z, w1.w);
#pragma unroll
      for (int r = 0; r < 6; r++) {
        float av = (kk == 0) ? a[r].x : (kk == 1) ? a[r].y : (kk == 2) ? a[r].z : a[r].w;
        ull aa = pack2(av, av);
        ffma2(acc[r][0], aa, w00);
        ffma2(acc[r][1], aa, w01);
        ffma2(acc[r][2], aa, w10);
        ffma2(acc[r][3], aa, w11);
      }
    }
  }
}

__device__ __forceinline__ void zacc(ull (&acc)[6][4]) {
#pragma unroll
  for (int r = 0; r < 6; r++)
#pragma unroll
    for (int c = 0; c < 4; c++) acc[r][c] = 0ull;
}

// group1: store raw partial sums into dst (junk cols land in LDA padding)
__device__ __forceinline__ void store_partial(ull (&acc)[6][4], float* __restrict__ dst,
                                              int tm, int tn) {
  if (tn >= 13) return;
  const int c0 = 4 * tn, c1 = 52 + 4 * tn;
#pragma unroll
  for (int r = 0; r < 6; r++) {
    int row = tm + 16 * r;
    float4 v0, v1;
    upk2(acc[r][0], v0.x, v0.y); upk2(acc[r][1], v0.z, v0.w);
    upk2(acc[r][2], v1.x, v1.y); upk2(acc[r][3], v1.z, v1.w);
    *reinterpret_cast<float4*>(dst + row * LDA + c0) = v0;
    *reinterpret_cast<float4*>(dst + row * LDA + c1) = v1;
  }
}

// group0: final = own partial + dst partial + bias (+resid) (relu opt) -> dst
__device__ __forceinline__ void epi_sum(ull (&acc)[6][4], const float* __restrict__ bias,
                                        int bmax, float* __restrict__ dst,
                                        const float* __restrict__ resid, bool dorelu,
                                        int tm, int tn) {
  if (tn >= 13) return;
  const int c0 = 4 * tn, c1 = 52 + 4 * tn;
  float4 b0, b1;
  b0.x = __ldg(bias + c0); b0.y = __ldg(bias + c0 + 1);
  b0.z = __ldg(bias + c0 + 2); b0.w = __ldg(bias + c0 + 3);
  b1.x = (c1 + 0 < bmax) ? __ldg(bias + c1 + 0) : 0.f;
  b1.y = (c1 + 1 < bmax) ? __ldg(bias + c1 + 1) : 0.f;
  b1.z = (c1 + 2 < bmax) ? __ldg(bias + c1 + 2) : 0.f;
  b1.w = (c1 + 3 < bmax) ? __ldg(bias + c1 + 3) : 0.f;
#pragma unroll
  for (int r = 0; r < 6; r++) {
    int row = tm + 16 * r;
    float4 p0 = *reinterpret_cast<const float4*>(dst + row * LDA + c0);
    float4 p1 = *reinterpret_cast<const float4*>(dst + row * LDA + c1);
    float4 v0, v1;
    upk2(acc[r][0], v0.x, v0.y); upk2(acc[r][1], v0.z, v0.w);
    upk2(acc[r][2], v1.x, v1.y); upk2(acc[r][3], v1.z, v1.w);
    v0.x += p0.x + b0.x; v0.y += p0.y + b0.y; v0.z += p0.z + b0.z; v0.w += p0.w + b0.w;
    v1.x += p1.x + b1.x; v1.y += p1.y + b1.y; v1.z += p1.z + b1.z; v1.w += p1.w + b1.w;
    if (resid) {
      float4 r0 = *reinterpret_cast<const float4*>(resid + row * LDA + c0);
      float4 r1 = *reinterpret_cast<const float4*>(resid + row * LDA + c1);
      v0.x += r0.x; v0.y += r0.y; v0.z += r0.z; v0.w += r0.w;
      v1.x += r1.x; v1.y += r1.y; v1.z += r1.z; v1.w += r1.w;
    }
    if (dorelu) {
      v0.x = fmaxf(v0.x, 0.f); v0.y = fmaxf(v0.y, 0.f);
      v0.z = fmaxf(v0.z, 0.f); v0.w = fmaxf(v0.w, 0.f);
      v1.x = fmaxf(v1.x, 0.f); v1.y = fmaxf(v1.y, 0.f);
      v1.z = fmaxf(v1.z, 0.f); v1.w = fmaxf(v1.w, 0.f);
    }
    *reinterpret_cast<float4*>(dst + row * LDA + c0) = v0;
    *reinterpret_cast<float4*>(dst + row * LDA + c1) = v1;
  }
}

__device__ __forceinline__ void layernorm_rows(const float* __restrict__ src,
                                               float* __restrict__ dst,
                                               const float* __restrict__ g,
                                               const float* __restrict__ b) {
  const int tid = threadIdx.x;
  if (tid < MROWS) {
    const float* y = src + tid * LDA;
    float m = 0.f;
#pragma unroll 4
    for (int d = 0; d < DM; d++) m += y[d];
    m *= (1.0f / DM);
    float v = 0.f;
#pragma unroll 4
    for (int d = 0; d < DM; d++) { float t = y[d] - m; v = fmaf(t, t, v); }
    v *= (1.0f / DM);
    float inv = rsqrtf(v + 1e-5f);
    float* o = dst + tid * LDA;
#pragma unroll 4
    for (int d = 0; d < DM; d++)
      o[d] = (y[d] - m) * inv * __ldg(g + d) + __ldg(b + d);
  }
}

__global__ void __launch_bounds__(THREADS, 1)
geomapnet_kernel(const float* __restrict__ x,
                 const float* __restrict__ We, const float* __restrict__ be,
                 const float* __restrict__ pe,
                 const float* __restrict__ Wq, const float* __restrict__ bq,
                 const float* __restrict__ Wk, const float* __restrict__ bk,
                 const float* __restrict__ Wv, const float* __restrict__ bv,
                 const float* __restrict__ Wo, const float* __restrict__ bo,
                 const float* __restrict__ ln1g, const float* __restrict__ ln1b,
                 const float* __restrict__ W1, const float* __restrict__ b1,
                 const float* __restrict__ W2, const float* __restrict__ b2,
                 const float* __restrict__ ln2g, const float* __restrict__ ln2b,
                 const float* __restrict__ Wf, const float* __restrict__ bf,
                 float* __restrict__ out)
{
  extern __shared__ float sm[];
  float* sX = sm + SX;
  float* sQ = sm + SQ;
  float* sK = sm + SK;
  float* sV = sm + SV;
  float* wt = sm + SWT;

  const int tid = threadIdx.x;
  const int grp = tid >> 8;           // 0 or 1
  const int gtid = tid & 255;
  const int tn = gtid & 15, tm = gtid >> 4;
  const int rowbase = blockIdx.x * MROWS;

  // ---- load x -> sQ[96][0..71], stage We^T (all threads) ----
  for (int idx = tid; idx < MROWS * (DIN / 4); idx += THREADS) {
    int r = idx / (DIN / 4), c4 = idx - r * (DIN / 4);
    *reinterpret_cast<float4*>(sQ + r * LDA + 4 * c4) =
        *reinterpret_cast<const float4*>(x + (size_t)(rowbase + r) * DIN + 4 * c4);
  }
  stage_wt(wt, We, DIN, DM, DIN, tid, THREADS);
  __syncthreads();

  // ---- embedding: X = x @ We^T + be + pe (K=72, split 36/36) ----
  {
    ull acc[6][4]; zacc(acc);
    int km = kmid(DIN);
    gemm_cp(sQ, wt, grp ? km : 0, grp ? DIN : km, acc, tm, tn);
    if (grp == 1) store_partial(acc, sX, tm, tn);
    __syncthreads();
    if (grp == 0 && tn < 13) {
      const int c0 = 4 * tn, c1 = 52 + 4 * tn;
#pragma unroll
      for (int r = 0; r < 6; r++) {
        int row = tm + 16 * r;
        int prow = (row % 3) * DM;
        float4 p0 = *reinterpret_cast<const float4*>(sX + row * LDA + c0);
        float4 p1 = *reinterpret_cast<const float4*>(sX + row * LDA + c1);
        float4 v0, v1;
        upk2(acc[0][0], v0.x, v0.x);  // placeholder overwritten below
        upk2(acc[r][0], v0.x, v0.y); upk2(acc[r][1], v0.z, v0.w);
        upk2(acc[r][2], v1.x, v1.y); upk2(acc[r][3], v1.z, v1.w);
        v0.x += p0.x + __ldg(be + c0) + __ldg(pe + prow + c0);
        v0.y += p0.y + __ldg(be + c0 + 1) + __ldg(pe + prow + c0 + 1);
        v0.z += p0.z + __ldg(be + c0 + 2) + __ldg(pe + prow + c0 + 2);
        v0.w += p0.w + __ldg(be + c0 + 3) + __ldg(pe + prow + c0 + 3);
        v1.x += p1.x + ((c1 + 0 < DM) ? __ldg(be + c1) + __ldg(pe + prow + c1) : 0.f);
        v1.y += p1.y + ((c1 + 1 < DM) ? __ldg(be + c1 + 1) + __ldg(pe + prow + c1 + 1) : 0.f);
        v1.z += p1.z + ((c1 + 2 < DM) ? __ldg(be + c1 + 2) + __ldg(pe + prow + c1 + 2) : 0.f);
        v1.w += p1.w + ((c1 + 3 < DM) ? __ldg(be + c1 + 3) + __ldg(pe + prow + c1 + 3) : 0.f);
        *reinterpret_cast<float4*>(sX + row * LDA + c0) = v0;
        *reinterpret_cast<float4*>(sX + row * LDA + c1) = v1;
      }
    }
    if (grp == 1) stage_wt(wt, Wq, DM, DM, DM, gtid, 256);
  }
  __syncthreads();

  const int kmD = kmid(DM);    // 52 for K=100
  // ---- encoder layers ----
  for (int li = 0; li < NLAYERS; li++) {
    // Q (wt = WqT)
    { ull a[6][4]; zacc(a);
      gemm_cp(sX, wt, grp ? kmD : 0, grp ? DM : kmD, a, tm, tn);
      if (grp == 1) store_partial(a, sQ, tm, tn);
      __syncthreads();
      if (grp == 0) epi_sum(a, bq + li * DM, DM, sQ, nullptr, false, tm, tn);
      else stage_wt(wt, Wk + li * DM * DM, DM, DM, DM, gtid, 256);
      __syncthreads(); }
    // K
    { ull a[6][4]; zacc(a);
      gemm_cp(sX, wt, grp ? kmD : 0, grp ? DM : kmD, a, tm, tn);
      if (grp == 1) store_partial(a, sK, tm, tn);
      __syncthreads();
      if (grp == 0) epi_sum(a, bk + li * DM, DM, sK, nullptr, false, tm, tn);
      else stage_wt(wt, Wv + li * DM * DM, DM, DM, DM, gtid, 256);
      __syncthreads(); }
    // V
    { ull a[6][4]; zacc(a);
      gemm_cp(sX, wt, grp ? kmD : 0, grp ? DM : kmD, a, tm, tn);
      if (grp == 1) store_partial(a, sV, tm, tn);
      __syncthreads();
      if (grp == 0) epi_sum(a, bv + li * DM, DM, sV, nullptr, false, tm, tn);
      else stage_wt(wt, Wo + li * DM * DM, DM, DM, DM, gtid, 256);
      __syncthreads(); }

    // attention (flat row-major head split), 320 tasks
    if (tid < TB * 10) {
      int e = tid / 10, h = tid - e * 10;
      const int base = h * 30;
      const float* Qe = sQ + (3 * e) * LDA;
      const float* Ke = sK + (3 * e) * LDA;
      const float* Ve = sV + (3 * e) * LDA;
      auto offf = [&](int f) { int s = f / 100; return s * LDA + (f - s * 100); };
      const float scale = 0.3162277660168379f;
      float att[3][3], q[30];
#pragma unroll
      for (int j = 0; j < 30; j++) q[j] = Qe[offf(base + j)];
#pragma unroll
      for (int b2_ = 0; b2_ < 3; b2_++) {
        float kk[10];
#pragma unroll
        for (int d3 = 0; d3 < 10; d3++) kk[d3] = Ke[offf(base + b2_ * 10 + d3)];
#pragma unroll
        for (int a2 = 0; a2 < 3; a2++) {
          float s2 = 0.f;
#pragma unroll
          for (int d3 = 0; d3 < 10; d3++) s2 = fmaf(q[a2 * 10 + d3], kk[d3], s2);
          att[a2][b2_] = s2 * scale;
        }
      }
#pragma unroll
      for (int a2 = 0; a2 < 3; a2++) {
        float mx = fmaxf(att[a2][0], fmaxf(att[a2][1], att[a2][2]));
        float sum = 0.f;
#pragma unroll
        for (int b2_ = 0; b2_ < 3; b2_++) { att[a2][b2_] = __expf(att[a2][b2_] - mx); sum += att[a2][b2_]; }
        float inv = 1.f / sum;
#pragma unroll
        for (int b2_ = 0; b2_ < 3; b2_++) att[a2][b2_] *= inv;
      }
      float* Qw = sQ + (3 * e) * LDA;
#pragma unroll
      for (int d3 = 0; d3 < 10; d3++) {
        float v0 = Ve[offf(base + d3)], v1 = Ve[offf(base + 10 + d3)], v2 = Ve[offf(base + 20 + d3)];
#pragma unroll
        for (int a2 = 0; a2 < 3; a2++)
          Qw[offf(base + a2 * 10 + d3)] = att[a2][0] * v0 + att[a2][1] * v1 + att[a2][2] * v2;
      }
    }
    __syncthreads();

    // O projection + residual -> sK
    { ull a[6][4]; zacc(a);
      gemm_cp(sQ, wt, grp ? kmD : 0, grp ? DM : kmD, a, tm, tn);
      if (grp == 1) store_partial(a, sK, tm, tn);
      __syncthreads();
      if (grp == 0) epi_sum(a, bo + li * DM, DM, sK, sX, false, tm, tn);
      else stage_wt(wt, W1 + (size_t)li * FFD * DM, DM, 104, DM, gtid, 256);
      __syncthreads(); }

    // LN1 -> sX
    layernorm_rows(sK, sX, ln1g + li * DM, ln1b + li * DM);
    __syncthreads();

    // ---- FFN: chunks of 104 hidden (last 96); yacc persists per group ----
    ull yacc[6][4]; zacc(yacc);
    int h0 = 0;
    for (int cc = 0; cc < 5; cc++) {
      int w = (cc < 4) ? 104 : 96;
      // FFN1: hidden = relu(X @ W1c^T + b1c) -> sV
      { ull f[6][4]; zacc(f);
        gemm_cp(sX, wt, grp ? kmD : 0, grp ? DM : kmD, f, tm, tn);
        if (grp == 1) store_partial(f, sV, tm, tn);
        __syncthreads();
        if (grp == 0) epi_sum(f, b1 + li * FFD + h0, w, sV, nullptr, true, tm, tn);
        else stage_wt(wt, W2 + (size_t)li * DM * FFD + h0, FFD, DM, w, gtid, 256);
        __syncthreads(); }
      // FFN2 accumulate
      { int kw = kmid(w);
        gemm_cp(sV, wt, grp ? kw : 0, grp ? w : kw, yacc, tm, tn); }
      __syncthreads();
      if (cc < 4) {
        int nw = (cc < 3) ? 104 : 96;
        stage_wt(wt, W1 + (size_t)li * FFD * DM + (size_t)(h0 + 104) * DM, DM, nw, DM, tid, THREADS);
        __syncthreads();
      }
      h0 += w;
    }
    // FFN final epilogue + residual -> sK
    if (grp == 1) store_partial(yacc, sK, tm, tn);
    __syncthreads();
    if (grp == 0) epi_sum(yacc, b2 + li * DM, DM, sK, sX, false, tm, tn);
    else if (li < NLAYERS - 1) stage_wt(wt, Wq + (li + 1) * DM * DM, DM, DM, DM, gtid, 256);
    __syncthreads();
    // LN2 -> sX
    layernorm_rows(sK, sX, ln2g + li * DM, ln2b + li * DM);
    __syncthreads();
  }

  // ---- classifier: out = flat(X)[300] @ Wf^T + bf (Wf from L2) ----
  for (int task = tid; task < TB * NCLS; task += THREADS) {
    int e = task / NCLS, c = task - e * NCLS;
    const float* Xe = sX + 3 * e * LDA;
    const float* wr = Wf + c * 300;
    float dot = __ldg(bf + c);
#pragma unroll
    for (int s = 0; s < 3; s++) {
      const float* xs = Xe + s * LDA;
      const float* ws = wr + s * DM;
#pragma unroll 5
      for (int d = 0; d < DM; d += 4) {
        float4 xv = *reinterpret_cast<const float4*>(xs + d);
        float4 wv = *reinterpret_cast<const float4*>(ws + d);
        dot = fmaf(xv.x, wv.x, dot); dot = fmaf(xv.y, wv.y, dot);
        dot = fmaf(xv.z, wv.z, dot); dot = fmaf(xv.w, wv.w, dot);
      }
    }
    out[(size_t)(blockIdx.x * TB + e) * NCLS + c] = dot;
  }
}

extern "C" void kernel_launch(void* const* d_in, const int* in_sizes, int n_in,
                              void* d_out, int out_size) {
  const float* x   = (const float*)d_in[0];
  const float* We  = (const float*)d_in[3];
  const float* be  = (const float*)d_in[4];
  const float* pe  = (const float*)d_in[5];
  const float* Wq  = (const float*)d_in[6];
  const float* bq  = (const float*)d_in[7];
  const float* Wk  = (const float*)d_in[8];
  const float* bk  = (const float*)d_in[9];
  const float* Wv  = (const float*)d_in[10];
  const float* bv  = (const float*)d_in[11];
  const float* Wo  = (const float*)d_in[12];
  const float* bo  = (const float*)d_in[13];
  const float* l1g = (const float*)d_in[14];
  const float* l1b = (const float*)d_in[15];
  const float* W1  = (const float*)d_in[16];
  const float* b1  = (const float*)d_in[17];
  const float* W2  = (const float*)d_in[18];
  const float* b2  = (const float*)d_in[19];
  const float* l2g = (const float*)d_in[20];
  const float* l2b = (const float*)d_in[21];
  const float* Wf  = (const float*)d_in[22];
  const float* bf  = (const float*)d_in[23];
  float* out = (float*)d_out;

  int Bsz = in_sizes[0] / (3 * DIN);       // 65536
  int nblocks = Bsz / TB;                  // 2048
  size_t smem = (size_t)SMEM_FLOATS * sizeof(float);  // 203,136 B

  cudaFuncSetAttribute(geomapnet_kernel,
                       cudaFuncAttributeMaxDynamicSharedMemorySize, (int)smem);
  geomapnet_kernel<<<nblocks, THREADS, smem>>>(x, We, be, pe, Wq, bq, Wk, bk, Wv, bv,
                                               Wo, bo, l1g, l1b, W1, b1, W2, b2,
                                               l2g, l2b, Wf, bf, out);
}

// round 10
// speedup vs baseline: 1.0968x; 1.0968x over previous
#include <cuda_runtime.h>

#define THREADS 128
#define TB 16
#define MROWS 48
#define LDA 104
#define LDWT 104
#define DM 100
#define DIN 72
#define FFD 512
#define NLAYERS 8
#define NCLS 40

// smem float offsets
#define SX 0
#define SQ 4992
#define SK 9984
#define SV 14976
#define SWT 19968
#define SMEM_FLOATS 25440   // 101,760 bytes (incl. 64-float tail pad for junk-lane reads) -> 2 CTAs/SM

typedef unsigned long long ull;

__device__ __forceinline__ void ffma2(ull& acc, ull a, ull b) {
  asm("fma.rn.f32x2 %0, %1, %2, %0;" : "+l"(acc) : "l"(a), "l"(b));
}
__device__ __forceinline__ ull pack2(float x, float y) {
  ull r; asm("mov.b64 %0, {%1, %2};" : "=l"(r) : "f"(x), "f"(y)); return r;
}
__device__ __forceinline__ void upk2(ull v, float& lo, float& hi) {
  asm("mov.b64 {%0, %1}, %2;" : "=f"(lo), "=f"(hi) : "l"(v));
}

// Stage W^T k-slice: wt[(k-kb)][n] = (n<nvalid) ? src[n*sstride + k] : 0, k in [kb,ke).
__device__ __forceinline__ void stage_wt(float* wt, const float* __restrict__ src,
                                         int sstride, int nvalid, int kb, int ke) {
  const int total = ((ke - kb) >> 2) * 104;
  for (int idx = threadIdx.x; idx < total; idx += THREADS) {
    int kc = idx / 104;
    int n = idx - kc * 104;
    float4 v = make_float4(0.f, 0.f, 0.f, 0.f);
    if (n < nvalid) v = *reinterpret_cast<const float4*>(src + n * sstride + kb + 4 * kc);
    int k4 = 4 * kc;
    wt[(k4 + 0) * LDWT + n] = v.x;
    wt[(k4 + 1) * LDWT + n] = v.y;
    wt[(k4 + 2) * LDWT + n] = v.z;
    wt[(k4 + 3) * LDWT + n] = v.w;
  }
}

// C[m][n] += sum_{k<Kr} A[m][k] * Wt[k][n]
// thread (tm 0-7, tn 0-15): rows {tm+8r, r<6}, cols {4tn..4tn+3} u {52+4tn..52+4tn+3}
__device__ __forceinline__ void gemm_cp(const float* __restrict__ A,
                                        const float* __restrict__ Wt,
                                        int Kr, ull (&acc)[6][4], int tm, int tn) {
  const float* a0 = A + tm * LDA;
  const int c0 = 4 * tn, c1 = 52 + 4 * tn;
#pragma unroll 2
  for (int k = 0; k < Kr; k += 4) {
    float4 a[6];
#pragma unroll
    for (int r = 0; r < 6; r++)
      a[r] = *reinterpret_cast<const float4*>(a0 + (8 * r) * LDA + k);
#pragma unroll
    for (int kk = 0; kk < 4; kk++) {
      const float* wrow = Wt + (k + kk) * LDWT;
      float4 w0 = *reinterpret_cast<const float4*>(wrow + c0);
      float4 w1 = *reinterpret_cast<const float4*>(wrow + c1);
      ull w00 = pack2(w0.x, w0.y), w01 = pack2(w0.z, w0.w);
      ull w10 = pack2(w1.x, w1.y), w11 = pack2(w1.z, w1.w);
#pragma unroll
      for (int r = 0; r < 6; r++) {
        float av = (kk == 0) ? a[r].x : (kk == 1) ? a[r].y : (kk == 2) ? a[r].z : a[r].w;
        ull aa = pack2(av, av);
        ffma2(acc[r][0], aa, w00);
        ffma2(acc[r][1], aa, w01);
        ffma2(acc[r][2], aa, w10);
        ffma2(acc[r][3], aa, w11);
      }
    }
  }
}

__device__ __forceinline__ void zacc(ull (&acc)[6][4]) {
#pragma unroll
  for (int r = 0; r < 6; r++)
#pragma unroll
    for (int c = 0; c < 4; c++) acc[r][c] = 0ull;
}

// K-split GEMM: stage half0 -> gemm -> stage half1 -> gemm. acc persists in regs.
// km/K must be multiples of 4. Caller epilogues, then __syncthreads.
__device__ __forceinline__ void gemm_ks(const float* __restrict__ A, float* wt,
                                        const float* __restrict__ Wsrc, int sstride,
                                        int nvalid, int K, int km,
                                        ull (&acc)[6][4], int tm, int tn) {
  stage_wt(wt, Wsrc, sstride, nvalid, 0, km);
  __syncthreads();
  gemm_cp(A, wt, km, acc, tm, tn);
  __syncthreads();
  stage_wt(wt, Wsrc, sstride, nvalid, km, K);
  __syncthreads();
  gemm_cp(A + km, wt, K - km, acc, tm, tn);
}

// final = acc + bias (+resid) (relu opt) -> dst. Junk cols (>=100) land in padding.
__device__ __forceinline__ void epi_cp(ull (&acc)[6][4], const float* __restrict__ bias,
                                       int bmax, float* __restrict__ dst,
                                       const float* __restrict__ resid, bool dorelu,
                                       int tm, int tn) {
  if (tn >= 13) return;
  const int c0 = 4 * tn, c1 = 52 + 4 * tn;
  float4 b0, b1;
  b0.x = __ldg(bias + c0); b0.y = __ldg(bias + c0 + 1);
  b0.z = __ldg(bias + c0 + 2); b0.w = __ldg(bias + c0 + 3);
  b1.x = (c1 + 0 < bmax) ? __ldg(bias + c1 + 0) : 0.f;
  b1.y = (c1 + 1 < bmax) ? __ldg(bias + c1 + 1) : 0.f;
  b1.z = (c1 + 2 < bmax) ? __ldg(bias + c1 + 2) : 0.f;
  b1.w = (c1 + 3 < bmax) ? __ldg(bias + c1 + 3) : 0.f;
#pragma unroll
  for (int r = 0; r < 6; r++) {
    int row = tm + 8 * r;
    float4 v0, v1;
    upk2(acc[r][0], v0.x, v0.y); upk2(acc[r][1], v0.z, v0.w);
    upk2(acc[r][2], v1.x, v1.y); upk2(acc[r][3], v1.z, v1.w);
    v0.x += b0.x; v0.y += b0.y; v0.z += b0.z; v0.w += b0.w;
    v1.x += b1.x; v1.y += b1.y; v1.z += b1.z; v1.w += b1.w;
    if (resid) {
      float4 r0 = *reinterpret_cast<const float4*>(resid + row * LDA + c0);
      float4 r1 = *reinterpret_cast<const float4*>(resid + row * LDA + c1);
      v0.x += r0.x; v0.y += r0.y; v0.z += r0.z; v0.w += r0.w;
      v1.x += r1.x; v1.y += r1.y; v1.z += r1.z; v1.w += r1.w;
    }
    if (dorelu) {
      v0.x = fmaxf(v0.x, 0.f); v0.y = fmaxf(v0.y, 0.f);
      v0.z = fmaxf(v0.z, 0.f); v0.w = fmaxf(v0.w, 0.f);
      v1.x = fmaxf(v1.x, 0.f); v1.y = fmaxf(v1.y, 0.f);
      v1.w = fmaxf(v1.w, 0.f); v1.z = fmaxf(v1.z, 0.f);
    }
    *reinterpret_cast<float4*>(dst + row * LDA + c0) = v0;
    *reinterpret_cast<float4*>(dst + row * LDA + c1) = v1;
  }
}

__device__ __forceinline__ void layernorm_rows(const float* __restrict__ src,
                                               float* __restrict__ dst,
                                               const float* __restrict__ g,
                                               const float* __restrict__ b) {
  const int tid = threadIdx.x;
  if (tid < MROWS) {
    const float* y = src + tid * LDA;
    float m = 0.f;
#pragma unroll 4
    for (int d = 0; d < DM; d++) m += y[d];
    m *= (1.0f / DM);
    float v = 0.f;
#pragma unroll 4
    for (int d = 0; d < DM; d++) { float t = y[d] - m; v = fmaf(t, t, v); }
    v *= (1.0f / DM);
    float inv = rsqrtf(v + 1e-5f);
    float* o = dst + tid * LDA;
#pragma unroll 4
    for (int d = 0; d < DM; d++)
      o[d] = (y[d] - m) * inv * __ldg(g + d) + __ldg(b + d);
  }
}

__global__ void __launch_bounds__(THREADS, 2)
geomapnet_kernel(const float* __restrict__ x,
                 const float* __restrict__ We, const float* __restrict__ be,
                 const float* __restrict__ pe,
                 const float* __restrict__ Wq, const float* __restrict__ bq,
                 const float* __restrict__ Wk, const float* __restrict__ bk,
                 const float* __restrict__ Wv, const float* __restrict__ bv,
                 const float* __restrict__ Wo, const float* __restrict__ bo,
                 const float* __restrict__ ln1g, const float* __restrict__ ln1b,
                 const float* __restrict__ W1, const float* __restrict__ b1,
                 const float* __restrict__ W2, const float* __restrict__ b2,
                 const float* __restrict__ ln2g, const float* __restrict__ ln2b,
                 const float* __restrict__ Wf, const float* __restrict__ bf,
                 float* __restrict__ out)
{
  extern __shared__ float sm[];
  float* sX = sm + SX;
  float* sQ = sm + SQ;
  float* sK = sm + SK;
  float* sV = sm + SV;
  float* wt = sm + SWT;

  const int tid = threadIdx.x;
  const int tn = tid & 15, tm = tid >> 4;
  const int rowbase = blockIdx.x * MROWS;

  // ---- load x -> sQ[48][0..71] ----
  for (int idx = tid; idx < MROWS * (DIN / 4); idx += THREADS) {
    int r = idx / (DIN / 4), c4 = idx - r * (DIN / 4);
    *reinterpret_cast<float4*>(sQ + r * LDA + 4 * c4) =
        *reinterpret_cast<const float4*>(x + (size_t)(rowbase + r) * DIN + 4 * c4);
  }
  __syncthreads();

  // ---- embedding: X = x @ We^T + be + pe (K=72, halves 36/36) ----
  {
    ull acc[6][4]; zacc(acc);
    gemm_ks(sQ, wt, We, DIN, DM, DIN, 36, acc, tm, tn);
    if (tn < 13) {
      const int c0 = 4 * tn, c1 = 52 + 4 * tn;
#pragma unroll
      for (int r = 0; r < 6; r++) {
        int row = tm + 8 * r;
        int prow = (row % 3) * DM;
        float4 v0, v1;
        upk2(acc[r][0], v0.x, v0.y); upk2(acc[r][1], v0.z, v0.w);
        upk2(acc[r][2], v1.x, v1.y); upk2(acc[r][3], v1.z, v1.w);
        v0.x += __ldg(be + c0) + __ldg(pe + prow + c0);
        v0.y += __ldg(be + c0 + 1) + __ldg(pe + prow + c0 + 1);
        v0.z += __ldg(be + c0 + 2) + __ldg(pe + prow + c0 + 2);
        v0.w += __ldg(be + c0 + 3) + __ldg(pe + prow + c0 + 3);
        if (c1 + 0 < DM) v1.x += __ldg(be + c1) + __ldg(pe + prow + c1);
        if (c1 + 1 < DM) v1.y += __ldg(be + c1 + 1) + __ldg(pe + prow + c1 + 1);
        if (c1 + 2 < DM) v1.z += __ldg(be + c1 + 2) + __ldg(pe + prow + c1 + 2);
        if (c1 + 3 < DM) v1.w += __ldg(be + c1 + 3) + __ldg(pe + prow + c1 + 3);
        *reinterpret_cast<float4*>(sX + row * LDA + c0) = v0;
        *reinterpret_cast<float4*>(sX + row * LDA + c1) = v1;
      }
    }
  }
  __syncthreads();

  // ---- encoder layers ----
  for (int li = 0; li < NLAYERS; li++) {
    // Q
    { ull a[6][4]; zacc(a);
      gemm_ks(sX, wt, Wq + li * DM * DM, DM, DM, DM, 52, a, tm, tn);
      epi_cp(a, bq + li * DM, DM, sQ, nullptr, false, tm, tn); }
    __syncthreads();
    // K
    { ull a[6][4]; zacc(a);
      gemm_ks(sX, wt, Wk + li * DM * DM, DM, DM, DM, 52, a, tm, tn);
      epi_cp(a, bk + li * DM, DM, sK, nullptr, false, tm, tn); }
    __syncthreads();
    // V
    { ull a[6][4]; zacc(a);
      gemm_ks(sX, wt, Wv + li * DM * DM, DM, DM, DM, 52, a, tm, tn);
      epi_cp(a, bv + li * DM, DM, sV, nullptr, false, tm, tn); }
    __syncthreads();

    // attention (flat row-major head split), TB*10 = 160 tasks
    for (int task = tid; task < TB * 10; task += THREADS) {
      int e = task / 10, h = task - e * 10;
      const int base = h * 30;
      const float* Qe = sQ + (3 * e) * LDA;
      const float* Ke = sK + (3 * e) * LDA;
      const float* Ve = sV + (3 * e) * LDA;
      auto offf = [&](int f) { int s = f / 100; return s * LDA + (f - s * 100); };
      const float scale = 0.3162277660168379f;
      float att[3][3], q[30];
#pragma unroll
      for (int j = 0; j < 30; j++) q[j] = Qe[offf(base + j)];
#pragma unroll
      for (int b2_ = 0; b2_ < 3; b2_++) {
        float kk[10];
#pragma unroll
        for (int d3 = 0; d3 < 10; d3++) kk[d3] = Ke[offf(base + b2_ * 10 + d3)];
#pragma unroll
        for (int a2 = 0; a2 < 3; a2++) {
          float s2 = 0.f;
#pragma unroll
          for (int d3 = 0; d3 < 10; d3++) s2 = fmaf(q[a2 * 10 + d3], kk[d3], s2);
          att[a2][b2_] = s2 * scale;
        }
      }
#pragma unroll
      for (int a2 = 0; a2 < 3; a2++) {
        float mx = fmaxf(att[a2][0], fmaxf(att[a2][1], att[a2][2]));
        float sum = 0.f;
#pragma unroll
        for (int b2_ = 0; b2_ < 3; b2_++) { att[a2][b2_] = __expf(att[a2][b2_] - mx); sum += att[a2][b2_]; }
        float inv = 1.f / sum;
#pragma unroll
        for (int b2_ = 0; b2_ < 3; b2_++) att[a2][b2_] *= inv;
      }
      float* Qw = sQ + (3 * e) * LDA;
#pragma unroll
      for (int d3 = 0; d3 < 10; d3++) {
        float v0 = Ve[offf(base + d3)], v1 = Ve[offf(base + 10 + d3)], v2 = Ve[offf(base + 20 + d3)];
#pragma unroll
        for (int a2 = 0; a2 < 3; a2++)
          Qw[offf(base + a2 * 10 + d3)] = att[a2][0] * v0 + att[a2][1] * v1 + att[a2][2] * v2;
      }
    }
    __syncthreads();

    // O projection + residual -> sK
    { ull a[6][4]; zacc(a);
      gemm_ks(sQ, wt, Wo + li * DM * DM, DM, DM, DM, 52, a, tm, tn);
      epi_cp(a, bo + li * DM, DM, sK, sX, false, tm, tn); }
    __syncthreads();
    // LN1 -> sX
    layernorm_rows(sK, sX, ln1g + li * DM, ln1b + li * DM);
    __syncthreads();

    // ---- FFN: chunks of 104 hidden (last 96); yacc persists ----
    ull yacc[6][4]; zacc(yacc);
    int h0 = 0;
    for (int cc = 0; cc < 5; cc++) {
      int w = (cc < 4) ? 104 : 96;
      // FFN1: hidden = relu(X @ W1c^T + b1c) -> sV (K=100, halves 52/48)
      { ull f[6][4]; zacc(f);
        gemm_ks(sX, wt, W1 + (size_t)li * FFD * DM + (size_t)h0 * DM, DM, w, DM, 52, f, tm, tn);
        epi_cp(f, b1 + li * FFD + h0, w, sV, nullptr, true, tm, tn); }
      __syncthreads();
      // FFN2: yacc += hidden @ W2c^T (K=w, halves)
      gemm_ks(sV, wt, W2 + (size_t)li * DM * FFD + h0, FFD, DM, w, (w >> 1) & ~3, yacc, tm, tn);
      __syncthreads();
      h0 += w;
    }
    // FFN final epilogue + residual -> sK
    epi_cp(yacc, b2 + li * DM, DM, sK, sX, false, tm, tn);
    __syncthreads();
    // LN2 -> sX
    layernorm_rows(sK, sX, ln2g + li * DM, ln2b + li * DM);
    __syncthreads();
  }

  // ---- classifier: out = flat(X)[300] @ Wf^T + bf (Wf from L2) ----
  for (int task = tid; task < TB * NCLS; task += THREADS) {
    int e = task / NCLS, c = task - e * NCLS;
    const float* Xe = sX + 3 * e * LDA;
    const float* wr = Wf + c * 300;
    float dot = __ldg(bf + c);
#pragma unroll
    for (int s = 0; s < 3; s++) {
      const float* xs = Xe + s * LDA;
      const float* ws = wr + s * DM;
#pragma unroll 5
      for (int d = 0; d < DM; d += 4) {
        float4 xv = *reinterpret_cast<const float4*>(xs + d);
        float4 wv = *reinterpret_cast<const float4*>(ws + d);
        dot = fmaf(xv.x, wv.x, dot); dot = fmaf(xv.y, wv.y, dot);
        dot = fmaf(xv.z, wv.z, dot); dot = fmaf(xv.w, wv.w, dot);
      }
    }
    out[(size_t)(blockIdx.x * TB + e) * NCLS + c] = dot;
  }
}

extern "C" void kernel_launch(void* const* d_in, const int* in_sizes, int n_in,
                              void* d_out, int out_size) {
  const float* x   = (const float*)d_in[0];
  const float* We  = (const float*)d_in[3];
  const float* be  = (const float*)d_in[4];
  const float* pe  = (const float*)d_in[5];
  const float* Wq  = (const float*)d_in[6];
  const float* bq  = (const float*)d_in[7];
  const float* Wk  = (const float*)d_in[8];
  const float* bk  = (const float*)d_in[9];
  const float* Wv  = (const float*)d_in[10];
  const float* bv  = (const float*)d_in[11];
  const float* Wo  = (const float*)d_in[12];
  const float* bo  = (const float*)d_in[13];
  const float* l1g = (const float*)d_in[14];
  const float* l1b = (const float*)d_in[15];
  const float* W1  = (const float*)d_in[16];
  const float* b1  = (const float*)d_in[17];
  const float* W2  = (const float*)d_in[18];
  const float* b2  = (const float*)d_in[19];
  const float* l2g = (const float*)d_in[20];
  const float* l2b = (const float*)d_in[21];
  const float* Wf  = (const float*)d_in[22];
  const float* bf  = (const float*)d_in[23];
  float* out = (float*)d_out;

  int Bsz = in_sizes[0] / (3 * DIN);       // 65536
  int nblocks = Bsz / TB;                  // 4096
  size_t smem = (size_t)SMEM_FLOATS * sizeof(float);  // 101,760 B

  cudaFuncSetAttribute(geomapnet_kernel,
                       cudaFuncAttributeMaxDynamicSharedMemorySize, (int)smem);
  geomapnet_kernel<<<nblocks, THREADS, smem>>>(x, We, be, pe, Wq, bq, Wk, bk, Wv, bv,
                                               Wo, bo, l1g, l1b, W1, b1, W2, b2,
                                               l2g, l2b, Wf, bf, out);
}